// round 16
// baseline (speedup 1.0000x reference)
#include <cuda_runtime.h>

#define ALPHA 0.9f
#define BETA  0.8f
#define TH    1.0f

typedef unsigned long long ull;

__device__ __forceinline__ ull fma2(ull a, ull b, ull c) {
    ull d;
    asm("fma.rn.f32x2 %0, %1, %2, %3;" : "=l"(d) : "l"(a), "l"(b), "l"(c));
    return d;
}
__device__ __forceinline__ ull pk2(float v) {
    ull r;
    asm("mov.b64 %0, {%1, %2};" : "=l"(r) : "f"(v), "f"(v));
    return r;
}
__device__ __forceinline__ void unpk(ull a, float& lo, float& hi) {
    asm("mov.b64 {%0, %1}, %2;" : "=f"(lo), "=f"(hi) : "l"(a));
}

// ---------------- scratch (device globals; no allocation) ----------------
__device__ float g_a1[128 * 32 * 55 * 55];
__device__ float g_a2[128 * 64 * 26 * 26];
__device__ float g_a3[128 * 64 * 24 * 24];
__device__ float g_part[145 * 128 * 128];
__device__ float g_spk1[10 * 128 * 128];
__device__ float g_spk2[10 * 128 * 256];
__device__ int   g_dummy[4];

// ---- tiny dummy: shifts the ncu capture window so a conv lands at slot 6 ----
__global__ void dummy_k(int i) {
    if (threadIdx.x == 0) g_dummy[i & 3] = i;
}

// =====================================================================
// conv1 (R14): (128,3,224,224)->(128,32,55,55), 8x8 s4, ReLU.
// grid (14,128), 512 thr, dyn smem 79296B (2 blocks/SM, 32 warps)
// =====================================================================
__global__ __launch_bounds__(512, 2) void conv1_k(const float* __restrict__ state,
                                                  const float* __restrict__ cw1,
                                                  const float* __restrict__ cb1) {
    extern __shared__ __align__(16) float sm[];
    float* s_in = sm;                 // [ic*20 + r][228], 13680 floats
    float* s_w  = sm + 13680;         // [rem][oc] stride 32, 6144 floats
    const int oyq = blockIdx.x, n = blockIdx.y, tid = threadIdx.x;

    for (int idx = tid; idx < 13440; idx += 512) {
        int row = idx / 224, ix = idx % 224;      // row = ic*20 + r
        int ic = row / 20, r = row % 20;
        int rg = 16 * oyq + r;
        if (rg < 224)
            s_in[row * 228 + ix] = state[((n * 3 + ic) * 224 + rg) * 224 + ix];
    }
    for (int idx = tid; idx < 6144; idx += 512) {
        int oc = idx / 192, rem = idx % 192;
        s_w[rem * 32 + oc] = cw1[idx];
    }
    __syncthreads();

    const int oyl = tid >> 7, t = tid & 127;
    const int ocg = t >> 5;           // warp-uniform
    const int p = t & 31;             // lane; active < 28
    const int oy = 4 * oyq + oyl;
    if (p < 28 && oy < 55) {
        ull acc[2][4];
#pragma unroll
        for (int i = 0; i < 2; i++)
#pragma unroll
            for (int j = 0; j < 4; j++) acc[i][j] = 0ull;

        for (int ic = 0; ic < 3; ic++)
#pragma unroll
            for (int ky = 0; ky < 8; ky++) {
                const float* ip = &s_in[(ic * 20 + oyl * 4 + ky) * 228 + 8 * p];
                float4 wa = *(const float4*)ip;
                float4 wb = *(const float4*)(ip + 4);
                float4 wc = *(const float4*)(ip + 8);
                float win[12] = {wa.x, wa.y, wa.z, wa.w, wb.x, wb.y, wb.z, wb.w,
                                 wc.x, wc.y, wc.z, wc.w};
                const int base = (ic * 64 + ky * 8) * 32 + ocg * 8;
#pragma unroll
                for (int kx = 0; kx < 8; kx++) {
                    ull x0 = pk2(win[kx]);
                    ull x1 = pk2(win[kx + 4]);
                    const ulonglong2* wp = (const ulonglong2*)&s_w[base + kx * 32];
                    ulonglong2 W0 = wp[0], W1 = wp[1];
                    acc[0][0] = fma2(x0, W0.x, acc[0][0]);
                    acc[0][1] = fma2(x0, W0.y, acc[0][1]);
                    acc[0][2] = fma2(x0, W1.x, acc[0][2]);
                    acc[0][3] = fma2(x0, W1.y, acc[0][3]);
                    acc[1][0] = fma2(x1, W0.x, acc[1][0]);
                    acc[1][1] = fma2(x1, W0.y, acc[1][1]);
                    acc[1][2] = fma2(x1, W1.x, acc[1][2]);
                    acc[1][3] = fma2(x1, W1.y, acc[1][3]);
                }
            }
        const int ox0 = 2 * p, ox1 = 2 * p + 1;
#pragma unroll
        for (int j = 0; j < 4; j++) {
            int oc = ocg * 8 + 2 * j;
            float b0v = cb1[oc], b1v = cb1[oc + 1];
            float l0, h0, l1, h1;
            unpk(acc[0][j], l0, h0);
            unpk(acc[1][j], l1, h1);
            float* op0 = &g_a1[((n * 32 + oc) * 55 + oy) * 55];
            float* op1 = op0 + 55 * 55;
            op0[ox0] = fmaxf(l0 + b0v, 0.f);
            op1[ox0] = fmaxf(h0 + b1v, 0.f);
            if (ox1 < 55) {
                op0[ox1] = fmaxf(l1 + b0v, 0.f);
                op1[ox1] = fmaxf(h1 + b1v, 0.f);
            }
        }
    }
}

// =====================================================================
// conv2 (R14): (128,32,55,55)->(128,64,26,26), 4x4 s2, ReLU.
// grid (7,128), 256 thr, dyn smem 52736B (4 blocks/SM, 32 warps)
// =====================================================================
__global__ __launch_bounds__(256, 4) void conv2_k(const float* __restrict__ cw2,
                                                  const float* __restrict__ cb2) {
    extern __shared__ __align__(16) float sm[];
    float* s_in = sm;                 // [icl*10 + r][56], 4480 floats
    float* s_w  = sm + 4480;          // [rem][oc] stride 68, 8704 floats
    const int oyq = blockIdx.x, n = blockIdx.y, tid = threadIdx.x;
    const int ocg = tid >> 5;         // warp-uniform, 0..7
    const int lane = tid & 31;        // active < 26
    const int oypl = lane / 13, oxp = lane % 13;
    const bool act = (lane < 26);
    ull acc[2][2][4];
#pragma unroll
    for (int a = 0; a < 2; a++)
#pragma unroll
        for (int b = 0; b < 2; b++)
#pragma unroll
            for (int j = 0; j < 4; j++) acc[a][b][j] = 0ull;

    for (int c = 0; c < 4; c++) {
        __syncthreads();
        for (int idx = tid; idx < 4400; idx += 256) {
            int icl = idx / 550, rem = idx % 550;
            int r = rem / 55, ix = rem % 55;
            int rg = 8 * oyq + r;
            s_in[(icl * 10 + r) * 56 + ix] =
                (rg < 55) ? g_a1[((n * 32 + c * 8 + icl) * 55 + rg) * 55 + ix] : 0.f;
        }
        for (int idx = tid; idx < 8192; idx += 256) {
            int oc = idx >> 7, rem = idx & 127;
            s_w[rem * 68 + oc] = cw2[oc * 512 + c * 128 + rem];
        }
        __syncthreads();
        if (act) {
            for (int icl = 0; icl < 8; icl++)
#pragma unroll
                for (int ky = 0; ky < 4; ky++) {
                    const float* r0 = &s_in[(icl * 10 + 4 * oypl + ky) * 56 + 4 * oxp];
                    const float* r1 = r0 + 2 * 56;
                    float2 a0 = *(const float2*)r0;
                    float2 a1 = *(const float2*)(r0 + 2);
                    float2 a2 = *(const float2*)(r0 + 4);
                    float2 c0 = *(const float2*)r1;
                    float2 c1 = *(const float2*)(r1 + 2);
                    float2 c2 = *(const float2*)(r1 + 4);
                    float xv[6] = {a0.x, a0.y, a1.x, a1.y, a2.x, a2.y};
                    float yv[6] = {c0.x, c0.y, c1.x, c1.y, c2.x, c2.y};
                    const int base = (icl * 16 + ky * 4) * 68 + ocg * 8;
#pragma unroll
                    for (int kx = 0; kx < 4; kx++) {
                        const ulonglong2* wp = (const ulonglong2*)&s_w[base + kx * 68];
                        ulonglong2 W0 = wp[0], W1 = wp[1];
                        ull x0 = pk2(xv[kx]), x1 = pk2(xv[kx + 2]);
                        ull y0 = pk2(yv[kx]), y1 = pk2(yv[kx + 2]);
                        acc[0][0][0] = fma2(x0, W0.x, acc[0][0][0]);
                        acc[0][0][1] = fma2(x0, W0.y, acc[0][0][1]);
                        acc[0][0][2] = fma2(x0, W1.x, acc[0][0][2]);
                        acc[0][0][3] = fma2(x0, W1.y, acc[0][0][3]);
                        acc[0][1][0] = fma2(x1, W0.x, acc[0][1][0]);
                        acc[0][1][1] = fma2(x1, W0.y, acc[0][1][1]);
                        acc[0][1][2] = fma2(x1, W1.x, acc[0][1][2]);
                        acc[0][1][3] = fma2(x1, W1.y, acc[0][1][3]);
                        acc[1][0][0] = fma2(y0, W0.x, acc[1][0][0]);
                        acc[1][0][1] = fma2(y0, W0.y, acc[1][0][1]);
                        acc[1][0][2] = fma2(y0, W1.x, acc[1][0][2]);
                        acc[1][0][3] = fma2(y0, W1.y, acc[1][0][3]);
                        acc[1][1][0] = fma2(y1, W0.x, acc[1][1][0]);
                        acc[1][1][1] = fma2(y1, W0.y, acc[1][1][1]);
                        acc[1][1][2] = fma2(y1, W1.x, acc[1][1][2]);
                        acc[1][1][3] = fma2(y1, W1.y, acc[1][1][3]);
                    }
                }
        }
    }
    if (act) {
#pragma unroll
        for (int loy = 0; loy < 2; loy++) {
            int oy = 4 * oyq + 2 * oypl + loy;
            if (oy < 26) {
#pragma unroll
                for (int lox = 0; lox < 2; lox++) {
                    int ox = 2 * oxp + lox;
#pragma unroll
                    for (int j = 0; j < 4; j++) {
                        int oc = ocg * 8 + 2 * j;
                        float lo, hi;
                        unpk(acc[loy][lox][j], lo, hi);
                        g_a2[((n * 64 + oc) * 26 + oy) * 26 + ox] = fmaxf(lo + cb2[oc], 0.f);
                        g_a2[((n * 64 + oc + 1) * 26 + oy) * 26 + ox] = fmaxf(hi + cb2[oc + 1], 0.f);
                    }
                }
            }
        }
    }
}

// =====================================================================
// conv3 (R14): (128,64,26,26)->(128,64,24,24), 3x3 s1, ReLU.
// grid (6,128), 256 thr, dyn smem 49920B (4 blocks/SM, 32 warps)
// =====================================================================
__global__ __launch_bounds__(256, 4) void conv3_k(const float* __restrict__ cw3,
                                                  const float* __restrict__ cb3) {
    extern __shared__ __align__(16) float sm[];
    float* s_in = sm;                 // [icl*6 + r][28], 2688 floats
    float* s_w  = sm + 2688;          // [rem][oc] stride 68, 9792 floats
    const int oyq = blockIdx.x, n = blockIdx.y, tid = threadIdx.x;
    const int ocg = tid >> 5;         // warp-uniform, 0..7
    const int lane = tid & 31;        // active < 24
    const int oypl = lane / 12, oxp = lane % 12;
    const bool act = (lane < 24);
    ull acc[2][2][4];
#pragma unroll
    for (int a = 0; a < 2; a++)
#pragma unroll
        for (int b = 0; b < 2; b++)
#pragma unroll
            for (int j = 0; j < 4; j++) acc[a][b][j] = 0ull;

    for (int c = 0; c < 4; c++) {
        __syncthreads();
        for (int idx = tid; idx < 2496; idx += 256) {
            int icl = idx / 156, rem = idx % 156;
            int r = rem / 26, ix = rem % 26;
            s_in[(icl * 6 + r) * 28 + ix] =
                g_a2[((n * 64 + c * 16 + icl) * 26 + 4 * oyq + r) * 26 + ix];
        }
        for (int idx = tid; idx < 9216; idx += 256) {
            int oc = idx / 144, rem = idx % 144;
            s_w[rem * 68 + oc] = cw3[oc * 576 + c * 144 + rem];
        }
        __syncthreads();
        if (act) {
            for (int icl = 0; icl < 16; icl++)
#pragma unroll
                for (int ky = 0; ky < 3; ky++) {
                    const float* r0 = &s_in[(icl * 6 + 2 * oypl + ky) * 28 + 2 * oxp];
                    const float* r1 = r0 + 28;
                    float2 a0 = *(const float2*)r0;
                    float2 a1 = *(const float2*)(r0 + 2);
                    float2 c0 = *(const float2*)r1;
                    float2 c1 = *(const float2*)(r1 + 2);
                    float xv[4] = {a0.x, a0.y, a1.x, a1.y};
                    float yv[4] = {c0.x, c0.y, c1.x, c1.y};
                    const int base = (icl * 9 + ky * 3) * 68 + ocg * 8;
#pragma unroll
                    for (int kx = 0; kx < 3; kx++) {
                        const ulonglong2* wp = (const ulonglong2*)&s_w[base + kx * 68];
                        ulonglong2 W0 = wp[0], W1 = wp[1];
                        ull x0 = pk2(xv[kx]), x1 = pk2(xv[kx + 1]);
                        ull y0 = pk2(yv[kx]), y1 = pk2(yv[kx + 1]);
                        acc[0][0][0] = fma2(x0, W0.x, acc[0][0][0]);
                        acc[0][0][1] = fma2(x0, W0.y, acc[0][0][1]);
                        acc[0][0][2] = fma2(x0, W1.x, acc[0][0][2]);
                        acc[0][0][3] = fma2(x0, W1.y, acc[0][0][3]);
                        acc[0][1][0] = fma2(x1, W0.x, acc[0][1][0]);
                        acc[0][1][1] = fma2(x1, W0.y, acc[0][1][1]);
                        acc[0][1][2] = fma2(x1, W1.x, acc[0][1][2]);
                        acc[0][1][3] = fma2(x1, W1.y, acc[0][1][3]);
                        acc[1][0][0] = fma2(y0, W0.x, acc[1][0][0]);
                        acc[1][0][1] = fma2(y0, W0.y, acc[1][0][1]);
                        acc[1][0][2] = fma2(y0, W1.x, acc[1][0][2]);
                        acc[1][0][3] = fma2(y0, W1.y, acc[1][0][3]);
                        acc[1][1][0] = fma2(y1, W0.x, acc[1][1][0]);
                        acc[1][1][1] = fma2(y1, W0.y, acc[1][1][1]);
                        acc[1][1][2] = fma2(y1, W1.x, acc[1][1][2]);
                        acc[1][1][3] = fma2(y1, W1.y, acc[1][1][3]);
                    }
                }
        }
    }
    if (act) {
#pragma unroll
        for (int loy = 0; loy < 2; loy++) {
            int oy = 4 * oyq + 2 * oypl + loy;
#pragma unroll
            for (int lox = 0; lox < 2; lox++) {
                int ox = 2 * oxp + lox;
#pragma unroll
                for (int j = 0; j < 4; j++) {
                    int oc = ocg * 8 + 2 * j;
                    float lo, hi;
                    unpk(acc[loy][lox][j], lo, hi);
                    g_a3[((n * 64 + oc) * 24 + oy) * 24 + ox] = fmaxf(lo + cb3[oc], 0.f);
                    g_a3[((n * 64 + oc + 1) * 24 + oy) * 24 + ox] = fmaxf(hi + cb3[oc + 1], 0.f);
                }
            }
        }
    }
}

// =====================================================================
// fc1 (R10 proven, 52us): split-K Kc=256, grid (2,2,145); 64x64 tile
// =====================================================================
__global__ __launch_bounds__(256) void fc1_k(const float* __restrict__ hist,
                                             const float* __restrict__ w1) {
    __shared__ __align__(16) float Xs[32 * 68];
    __shared__ __align__(16) float Ws[32 * 68];
    const int kb = blockIdx.z, b0 = blockIdx.x * 64, j0 = blockIdx.y * 64;
    const int tid = threadIdx.x;
    const int klen = (kb == 144) ? 90 : 256;
    const int kbase = kb * 256;
    const int tb = tid & 15, tj = tid >> 4;
    ull acc[4][2];
#pragma unroll
    for (int i = 0; i < 4; i++) { acc[i][0] = 0ull; acc[i][1] = 0ull; }

    for (int ks = 0; ks < klen; ks += 32) {
        __syncthreads();
#pragma unroll
        for (int i = 0; i < 4; i++) {
            int e = tid + i * 256;
            int b = e >> 4, kh = e & 15;
            int k = ks + kh * 2;
            float2 xv = make_float2(0.f, 0.f), wv = make_float2(0.f, 0.f);
            if (k < klen) {
                xv = (kb == 144) ? *(const float2*)&hist[(b0 + b) * 90 + k]
                                 : *(const float2*)&g_a3[(b0 + b) * 36864 + kbase + k];
                wv = *(const float2*)&w1[(j0 + b) * 36954 + kbase + k];
            }
            Xs[(kh * 2) * 68 + b] = xv.x;
            Xs[(kh * 2 + 1) * 68 + b] = xv.y;
            Ws[(kh * 2) * 68 + b] = wv.x;
            Ws[(kh * 2 + 1) * 68 + b] = wv.y;
        }
        __syncthreads();
#pragma unroll
        for (int kk = 0; kk < 32; kk++) {
            ulonglong2 W = *(const ulonglong2*)&Ws[kk * 68 + tj * 4];
#pragma unroll
            for (int i = 0; i < 4; i++) {
                ull xp = pk2(Xs[kk * 68 + tb * 4 + i]);
                acc[i][0] = fma2(xp, W.x, acc[i][0]);
                acc[i][1] = fma2(xp, W.y, acc[i][1]);
            }
        }
    }
#pragma unroll
    for (int i = 0; i < 4; i++) {
        float* op = &g_part[(kb * 128 + b0 + tb * 4 + i) * 128 + j0 + tj * 4];
        float lo, hi;
        unpk(acc[i][0], lo, hi);
        op[0] = lo; op[1] = hi;
        unpk(acc[i][1], lo, hi);
        op[2] = lo; op[3] = hi;
    }
}

// =====================================================================
// lif1: reduce partials -> h1 (+b1); full stage-1 trajectory.
// 256 blocks x 64 thr (was 64x256: only 64/148 SMs busy)
// =====================================================================
__global__ __launch_bounds__(64) void lif1_k(const float* __restrict__ b1) {
    int gid = blockIdx.x * 64 + threadIdx.x;
    int j = gid & 127;
    float h = b1[j];
#pragma unroll
    for (int kb = 0; kb < 145; kb++) h += g_part[kb * 16384 + gid];
    float mem = 0.f, syn = 0.f;
#pragma unroll
    for (int t = 0; t < 10; t++) {
        syn = ALPHA * syn + h;
        mem = BETA * mem + syn;
        float s = (mem > TH) ? 1.f : 0.f;
        mem -= s * TH;
        g_spk1[t * 16384 + gid] = s;
    }
}

// =====================================================================
// gemm2+lif2 FUSED: each block owns a 32b x 32j tile for ALL 10 timesteps;
// LIF state carried in registers; writes spk2 directly (h2 never hits gmem).
// grid (4,8), 256 thr. Accumulation order identical to old gemm2 (k ascending,
// fma, +b2 at end) -> h2 and spk2 bit-identical.
// =====================================================================
__global__ __launch_bounds__(256) void gemm2lif2_k(const float* __restrict__ w2,
                                                   const float* __restrict__ b2) {
    __shared__ float Ws[32 * 129];
    __shared__ float Xs[32 * 129];
    const int bb = blockIdx.x * 32, jb = blockIdx.y * 32;
    const int tid = threadIdx.x;
    const int tj = tid >> 3;          // 0..31: j index
    const int tbg = (tid & 7) * 4;    // b group of 4

    for (int idx = tid; idx < 4096; idx += 256) {
        int r = idx >> 7, k = idx & 127;
        Ws[r * 129 + k] = w2[(jb + r) * 128 + k];
    }
    const float bj = b2[jb + tj];

    float mem[4] = {0.f, 0.f, 0.f, 0.f};
    float syn[4] = {0.f, 0.f, 0.f, 0.f};

    for (int t = 0; t < 10; t++) {
        __syncthreads();
        for (int idx = tid; idx < 4096; idx += 256) {
            int r = idx >> 7, k = idx & 127;
            Xs[r * 129 + k] = g_spk1[t * 16384 + (bb + r) * 128 + k];
        }
        __syncthreads();
        float acc[4] = {0.f, 0.f, 0.f, 0.f};
        for (int k = 0; k < 128; k++) {
            float wv = Ws[tj * 129 + k];
#pragma unroll
            for (int i = 0; i < 4; i++)
                acc[i] += Xs[(tbg + i) * 129 + k] * wv;
        }
#pragma unroll
        for (int i = 0; i < 4; i++) {
            float h = acc[i] + bj;
            syn[i] = ALPHA * syn[i] + h;
            mem[i] = BETA * mem[i] + syn[i];
            float s = (mem[i] > TH) ? 1.f : 0.f;
            mem[i] -= s * TH;
            g_spk2[(t * 128 + bb + tbg + i) * 256 + jb + tj] = s;
        }
    }
}

// =====================================================================
__global__ __launch_bounds__(96) void out_k(const float* __restrict__ w3,
                                            const float* __restrict__ b3,
                                            float* __restrict__ out) {
    __shared__ float s_s[10 * 256];
    __shared__ float s_w[9 * 256];
    __shared__ float s_h[90];
    const int b = blockIdx.x, tid = threadIdx.x;

    for (int idx = tid; idx < 2560; idx += 96) {
        int t = idx >> 8, k = idx & 255;
        s_s[idx] = g_spk2[(t * 128 + b) * 256 + k];
    }
    for (int idx = tid; idx < 2304; idx += 96) s_w[idx] = w3[idx];
    __syncthreads();

    if (tid < 90) {
        int t = tid / 9, o = tid % 9;
        float a = b3[o];
        for (int k = 0; k < 256; k++) a += s_s[t * 256 + k] * s_w[o * 256 + k];
        s_h[tid] = a;
    }
    __syncthreads();

    if (tid < 9) {
        float syn = 0.f, mem = 0.f, pot = 0.f;
#pragma unroll
        for (int t = 0; t < 10; t++) {
            syn = ALPHA * syn + s_h[t * 9 + tid];
            mem = BETA * mem + syn;
            pot += mem;
        }
        out[b * 9 + tid] = pot / 10.0f;
    }
}

// =====================================================================
extern "C" void kernel_launch(void* const* d_in, const int* in_sizes, int n_in,
                              void* d_out, int out_size) {
    const float* state = (const float*)d_in[0];
    const float* hist  = (const float*)d_in[1];
    const float* cw1 = (const float*)d_in[2];
    const float* cb1 = (const float*)d_in[3];
    const float* cw2 = (const float*)d_in[4];
    const float* cb2 = (const float*)d_in[5];
    const float* cw3 = (const float*)d_in[6];
    const float* cb3 = (const float*)d_in[7];
    const float* w1  = (const float*)d_in[8];
    const float* b1  = (const float*)d_in[9];
    const float* w2  = (const float*)d_in[10];
    const float* b2  = (const float*)d_in[11];
    const float* w3  = (const float*)d_in[12];
    const float* b3  = (const float*)d_in[13];
    float* out = (float*)d_out;

    const int smem1 = 79296, smem2 = 52736, smem3 = 49920;
    cudaFuncSetAttribute(conv1_k, cudaFuncAttributeMaxDynamicSharedMemorySize, smem1);
    cudaFuncSetAttribute(conv2_k, cudaFuncAttributeMaxDynamicSharedMemorySize, smem2);
    cudaFuncSetAttribute(conv3_k, cudaFuncAttributeMaxDynamicSharedMemorySize, smem3);

    // 3 tiny launches: shift ncu's capture slot (skip-5) onto conv1_k.
    dummy_k<<<1, 32>>>(0);
    dummy_k<<<1, 32>>>(1);
    dummy_k<<<1, 32>>>(2);

    conv1_k<<<dim3(14, 128), 512, smem1>>>(state, cw1, cb1);
    conv2_k<<<dim3(7, 128), 256, smem2>>>(cw2, cb2);
    conv3_k<<<dim3(6, 128), 256, smem3>>>(cw3, cb3);
    fc1_k<<<dim3(2, 2, 145), 256>>>(hist, w1);
    lif1_k<<<256, 64>>>(b1);
    gemm2lif2_k<<<dim3(4, 8), 256>>>(w2, b2);
    out_k<<<128, 96>>>(w3, b3, out);
}

// round 17
// speedup vs baseline: 1.0631x; 1.0631x over previous
#include <cuda_runtime.h>

#define ALPHA 0.9f
#define BETA  0.8f
#define TH    1.0f

typedef unsigned long long ull;

__device__ __forceinline__ ull fma2(ull a, ull b, ull c) {
    ull d;
    asm("fma.rn.f32x2 %0, %1, %2, %3;" : "=l"(d) : "l"(a), "l"(b), "l"(c));
    return d;
}
__device__ __forceinline__ ull pk2(float v) {
    ull r;
    asm("mov.b64 %0, {%1, %2};" : "=l"(r) : "f"(v), "f"(v));
    return r;
}
__device__ __forceinline__ void unpk(ull a, float& lo, float& hi) {
    asm("mov.b64 {%0, %1}, %2;" : "=f"(lo), "=f"(hi) : "l"(a));
}

// ---------------- scratch (device globals; no allocation) ----------------
__device__ float g_a1[128 * 32 * 55 * 55];
__device__ float g_a2[128 * 64 * 26 * 26];
__device__ float g_a3[128 * 64 * 24 * 24];
__device__ float g_part[145 * 128 * 128];
__device__ float g_spk1[10 * 128 * 128];
__device__ float g_h2[10 * 128 * 256];
__device__ float g_spk2[10 * 128 * 256];
__device__ int   g_dummy[4];

__global__ void dummy_k(int i) {
    if (threadIdx.x == 0) g_dummy[i & 3] = i;
}

// =====================================================================
// conv1: (128,3,224,224)->(128,32,55,55), 8x8 s4, ReLU.
// grid (14,128), 512 thr, dyn smem 79296B (2 blocks/SM, 32 warps)
// LANE RE-BIN: warp = 4 ocg x 8 spatial-pairs (ocg = lane>>3, sp = lane&7,
// p = warpInOy*8 + sp). Input LDS.128: 8 distinct addrs/warp (2-way) vs 28
// distinct (7-way) before. Weight LDS.128: 4 distinct (1 wavefront).
// Per-thread math identical to R14 -> bit-identical outputs.
// =====================================================================
__global__ __launch_bounds__(512, 2) void conv1_k(const float* __restrict__ state,
                                                  const float* __restrict__ cw1,
                                                  const float* __restrict__ cb1) {
    extern __shared__ __align__(16) float sm[];
    float* s_in = sm;                 // [ic*20 + r][228], 13680 floats
    float* s_w  = sm + 13680;         // [rem][oc] stride 32, 6144 floats
    const int oyq = blockIdx.x, n = blockIdx.y, tid = threadIdx.x;

    for (int idx = tid; idx < 13440; idx += 512) {
        int row = idx / 224, ix = idx % 224;      // row = ic*20 + r
        int ic = row / 20, r = row % 20;
        int rg = 16 * oyq + r;
        if (rg < 224)
            s_in[row * 228 + ix] = state[((n * 3 + ic) * 224 + rg) * 224 + ix];
    }
    for (int idx = tid; idx < 6144; idx += 512) {
        int oc = idx / 192, rem = idx % 192;
        s_w[rem * 32 + oc] = cw1[idx];
    }
    __syncthreads();

    const int oyl = tid >> 7, t = tid & 127;
    const int wiy = t >> 5;           // warp within oy group, 0..3
    const int lane = t & 31;
    const int ocg = lane >> 3;        // 0..3 (4 per warp)
    const int sp = lane & 7;          // 0..7 spatial slots per warp
    const int p = wiy * 8 + sp;       // pair index, active < 28
    const int oy = 4 * oyq + oyl;
    if (p < 28 && oy < 55) {
        ull acc[2][4];
#pragma unroll
        for (int i = 0; i < 2; i++)
#pragma unroll
            for (int j = 0; j < 4; j++) acc[i][j] = 0ull;

        for (int ic = 0; ic < 3; ic++)
#pragma unroll
            for (int ky = 0; ky < 8; ky++) {
                const float* ip = &s_in[(ic * 20 + oyl * 4 + ky) * 228 + 8 * p];
                float4 wa = *(const float4*)ip;
                float4 wb = *(const float4*)(ip + 4);
                float4 wc = *(const float4*)(ip + 8);
                float win[12] = {wa.x, wa.y, wa.z, wa.w, wb.x, wb.y, wb.z, wb.w,
                                 wc.x, wc.y, wc.z, wc.w};
                const int base = (ic * 64 + ky * 8) * 32 + ocg * 8;
#pragma unroll
                for (int kx = 0; kx < 8; kx++) {
                    ull x0 = pk2(win[kx]);
                    ull x1 = pk2(win[kx + 4]);
                    const ulonglong2* wp = (const ulonglong2*)&s_w[base + kx * 32];
                    ulonglong2 W0 = wp[0], W1 = wp[1];
                    acc[0][0] = fma2(x0, W0.x, acc[0][0]);
                    acc[0][1] = fma2(x0, W0.y, acc[0][1]);
                    acc[0][2] = fma2(x0, W1.x, acc[0][2]);
                    acc[0][3] = fma2(x0, W1.y, acc[0][3]);
                    acc[1][0] = fma2(x1, W0.x, acc[1][0]);
                    acc[1][1] = fma2(x1, W0.y, acc[1][1]);
                    acc[1][2] = fma2(x1, W1.x, acc[1][2]);
                    acc[1][3] = fma2(x1, W1.y, acc[1][3]);
                }
            }
        const int ox0 = 2 * p, ox1 = 2 * p + 1;
#pragma unroll
        for (int j = 0; j < 4; j++) {
            int oc = ocg * 8 + 2 * j;
            float b0v = cb1[oc], b1v = cb1[oc + 1];
            float l0, h0, l1, h1;
            unpk(acc[0][j], l0, h0);
            unpk(acc[1][j], l1, h1);
            float* op0 = &g_a1[((n * 32 + oc) * 55 + oy) * 55];
            float* op1 = op0 + 55 * 55;
            op0[ox0] = fmaxf(l0 + b0v, 0.f);
            op1[ox0] = fmaxf(h0 + b1v, 0.f);
            if (ox1 < 55) {
                op0[ox1] = fmaxf(l1 + b0v, 0.f);
                op1[ox1] = fmaxf(h1 + b1v, 0.f);
            }
        }
    }
}

// =====================================================================
// conv2: (128,32,55,55)->(128,64,26,26), 4x4 s2, ReLU.
// grid (7,128), 256 thr, dyn smem 52736B (4 blocks/SM, 32 warps)
// LANE RE-BIN: warp = 4 ocg x 8 spatial (ocg = (w>>2)*4 + (lane&3),
// s = (w&3)*8 + (lane>>2), active s<26). Math identical to R14.
// =====================================================================
__global__ __launch_bounds__(256, 4) void conv2_k(const float* __restrict__ cw2,
                                                  const float* __restrict__ cb2) {
    extern __shared__ __align__(16) float sm[];
    float* s_in = sm;                 // [icl*10 + r][56], 4480 floats
    float* s_w  = sm + 4480;          // [rem][oc] stride 68, 8704 floats
    const int oyq = blockIdx.x, n = blockIdx.y, tid = threadIdx.x;
    const int w = tid >> 5, lane = tid & 31;
    const int ocg = ((w >> 2) << 2) + (lane & 3);   // 0..7
    const int s = ((w & 3) << 3) + (lane >> 2);     // 0..31, active < 26
    const bool act = (s < 26);
    const int oypl = s / 13, oxp = s % 13;
    ull acc[2][2][4];
#pragma unroll
    for (int a = 0; a < 2; a++)
#pragma unroll
        for (int b = 0; b < 2; b++)
#pragma unroll
            for (int j = 0; j < 4; j++) acc[a][b][j] = 0ull;

    for (int c = 0; c < 4; c++) {
        __syncthreads();
        for (int idx = tid; idx < 4400; idx += 256) {
            int icl = idx / 550, rem = idx % 550;
            int r = rem / 55, ix = rem % 55;
            int rg = 8 * oyq + r;
            s_in[(icl * 10 + r) * 56 + ix] =
                (rg < 55) ? g_a1[((n * 32 + c * 8 + icl) * 55 + rg) * 55 + ix] : 0.f;
        }
        for (int idx = tid; idx < 8192; idx += 256) {
            int oc = idx >> 7, rem = idx & 127;
            s_w[rem * 68 + oc] = cw2[oc * 512 + c * 128 + rem];
        }
        __syncthreads();
        if (act) {
            for (int icl = 0; icl < 8; icl++)
#pragma unroll
                for (int ky = 0; ky < 4; ky++) {
                    const float* r0 = &s_in[(icl * 10 + 4 * oypl + ky) * 56 + 4 * oxp];
                    const float* r1 = r0 + 2 * 56;
                    float2 a0 = *(const float2*)r0;
                    float2 a1 = *(const float2*)(r0 + 2);
                    float2 a2 = *(const float2*)(r0 + 4);
                    float2 c0 = *(const float2*)r1;
                    float2 c1 = *(const float2*)(r1 + 2);
                    float2 c2 = *(const float2*)(r1 + 4);
                    float xv[6] = {a0.x, a0.y, a1.x, a1.y, a2.x, a2.y};
                    float yv[6] = {c0.x, c0.y, c1.x, c1.y, c2.x, c2.y};
                    const int base = (icl * 16 + ky * 4) * 68 + ocg * 8;
#pragma unroll
                    for (int kx = 0; kx < 4; kx++) {
                        const ulonglong2* wp = (const ulonglong2*)&s_w[base + kx * 68];
                        ulonglong2 W0 = wp[0], W1 = wp[1];
                        ull x0 = pk2(xv[kx]), x1 = pk2(xv[kx + 2]);
                        ull y0 = pk2(yv[kx]), y1 = pk2(yv[kx + 2]);
                        acc[0][0][0] = fma2(x0, W0.x, acc[0][0][0]);
                        acc[0][0][1] = fma2(x0, W0.y, acc[0][0][1]);
                        acc[0][0][2] = fma2(x0, W1.x, acc[0][0][2]);
                        acc[0][0][3] = fma2(x0, W1.y, acc[0][0][3]);
                        acc[0][1][0] = fma2(x1, W0.x, acc[0][1][0]);
                        acc[0][1][1] = fma2(x1, W0.y, acc[0][1][1]);
                        acc[0][1][2] = fma2(x1, W1.x, acc[0][1][2]);
                        acc[0][1][3] = fma2(x1, W1.y, acc[0][1][3]);
                        acc[1][0][0] = fma2(y0, W0.x, acc[1][0][0]);
                        acc[1][0][1] = fma2(y0, W0.y, acc[1][0][1]);
                        acc[1][0][2] = fma2(y0, W1.x, acc[1][0][2]);
                        acc[1][0][3] = fma2(y0, W1.y, acc[1][0][3]);
                        acc[1][1][0] = fma2(y1, W0.x, acc[1][1][0]);
                        acc[1][1][1] = fma2(y1, W0.y, acc[1][1][1]);
                        acc[1][1][2] = fma2(y1, W1.x, acc[1][1][2]);
                        acc[1][1][3] = fma2(y1, W1.y, acc[1][1][3]);
                    }
                }
        }
    }
    if (act) {
#pragma unroll
        for (int loy = 0; loy < 2; loy++) {
            int oy = 4 * oyq + 2 * oypl + loy;
            if (oy < 26) {
#pragma unroll
                for (int lox = 0; lox < 2; lox++) {
                    int ox = 2 * oxp + lox;
#pragma unroll
                    for (int j = 0; j < 4; j++) {
                        int oc = ocg * 8 + 2 * j;
                        float lo, hi;
                        unpk(acc[loy][lox][j], lo, hi);
                        g_a2[((n * 64 + oc) * 26 + oy) * 26 + ox] = fmaxf(lo + cb2[oc], 0.f);
                        g_a2[((n * 64 + oc + 1) * 26 + oy) * 26 + ox] = fmaxf(hi + cb2[oc + 1], 0.f);
                    }
                }
            }
        }
    }
}

// =====================================================================
// conv3: (128,64,26,26)->(128,64,24,24), 3x3 s1, ReLU.
// grid (6,128), 256 thr, dyn smem 49920B (4 blocks/SM, 32 warps)
// LANE RE-BIN: same 4-ocg x 8-spatial warp shape, active s<24.
// =====================================================================
__global__ __launch_bounds__(256, 4) void conv3_k(const float* __restrict__ cw3,
                                                  const float* __restrict__ cb3) {
    extern __shared__ __align__(16) float sm[];
    float* s_in = sm;                 // [icl*6 + r][28], 2688 floats
    float* s_w  = sm + 2688;          // [rem][oc] stride 68, 9792 floats
    const int oyq = blockIdx.x, n = blockIdx.y, tid = threadIdx.x;
    const int w = tid >> 5, lane = tid & 31;
    const int ocg = ((w >> 2) << 2) + (lane & 3);   // 0..7
    const int s = ((w & 3) << 3) + (lane >> 2);     // 0..31, active < 24
    const bool act = (s < 24);
    const int oypl = s / 12, oxp = s % 12;
    ull acc[2][2][4];
#pragma unroll
    for (int a = 0; a < 2; a++)
#pragma unroll
        for (int b = 0; b < 2; b++)
#pragma unroll
            for (int j = 0; j < 4; j++) acc[a][b][j] = 0ull;

    for (int c = 0; c < 4; c++) {
        __syncthreads();
        for (int idx = tid; idx < 2496; idx += 256) {
            int icl = idx / 156, rem = idx % 156;
            int r = rem / 26, ix = rem % 26;
            s_in[(icl * 6 + r) * 28 + ix] =
                g_a2[((n * 64 + c * 16 + icl) * 26 + 4 * oyq + r) * 26 + ix];
        }
        for (int idx = tid; idx < 9216; idx += 256) {
            int oc = idx / 144, rem = idx % 144;
            s_w[rem * 68 + oc] = cw3[oc * 576 + c * 144 + rem];
        }
        __syncthreads();
        if (act) {
            for (int icl = 0; icl < 16; icl++)
#pragma unroll
                for (int ky = 0; ky < 3; ky++) {
                    const float* r0 = &s_in[(icl * 6 + 2 * oypl + ky) * 28 + 2 * oxp];
                    const float* r1 = r0 + 28;
                    float2 a0 = *(const float2*)r0;
                    float2 a1 = *(const float2*)(r0 + 2);
                    float2 c0 = *(const float2*)r1;
                    float2 c1 = *(const float2*)(r1 + 2);
                    float xv[4] = {a0.x, a0.y, a1.x, a1.y};
                    float yv[4] = {c0.x, c0.y, c1.x, c1.y};
                    const int base = (icl * 9 + ky * 3) * 68 + ocg * 8;
#pragma unroll
                    for (int kx = 0; kx < 3; kx++) {
                        const ulonglong2* wp = (const ulonglong2*)&s_w[base + kx * 68];
                        ulonglong2 W0 = wp[0], W1 = wp[1];
                        ull x0 = pk2(xv[kx]), x1 = pk2(xv[kx + 1]);
                        ull y0 = pk2(yv[kx]), y1 = pk2(yv[kx + 1]);
                        acc[0][0][0] = fma2(x0, W0.x, acc[0][0][0]);
                        acc[0][0][1] = fma2(x0, W0.y, acc[0][0][1]);
                        acc[0][0][2] = fma2(x0, W1.x, acc[0][0][2]);
                        acc[0][0][3] = fma2(x0, W1.y, acc[0][0][3]);
                        acc[0][1][0] = fma2(x1, W0.x, acc[0][1][0]);
                        acc[0][1][1] = fma2(x1, W0.y, acc[0][1][1]);
                        acc[0][1][2] = fma2(x1, W1.x, acc[0][1][2]);
                        acc[0][1][3] = fma2(x1, W1.y, acc[0][1][3]);
                        acc[1][0][0] = fma2(y0, W0.x, acc[1][0][0]);
                        acc[1][0][1] = fma2(y0, W0.y, acc[1][0][1]);
                        acc[1][0][2] = fma2(y0, W1.x, acc[1][0][2]);
                        acc[1][0][3] = fma2(y0, W1.y, acc[1][0][3]);
                        acc[1][1][0] = fma2(y1, W0.x, acc[1][1][0]);
                        acc[1][1][1] = fma2(y1, W0.y, acc[1][1][1]);
                        acc[1][1][2] = fma2(y1, W1.x, acc[1][1][2]);
                        acc[1][1][3] = fma2(y1, W1.y, acc[1][1][3]);
                    }
                }
        }
    }
    if (act) {
#pragma unroll
        for (int loy = 0; loy < 2; loy++) {
            int oy = 4 * oyq + 2 * oypl + loy;
#pragma unroll
            for (int lox = 0; lox < 2; lox++) {
                int ox = 2 * oxp + lox;
#pragma unroll
                for (int j = 0; j < 4; j++) {
                    int oc = ocg * 8 + 2 * j;
                    float lo, hi;
                    unpk(acc[loy][lox][j], lo, hi);
                    g_a3[((n * 64 + oc) * 24 + oy) * 24 + ox] = fmaxf(lo + cb3[oc], 0.f);
                    g_a3[((n * 64 + oc + 1) * 24 + oy) * 24 + ox] = fmaxf(hi + cb3[oc + 1], 0.f);
                }
            }
        }
    }
}

// =====================================================================
// fc1 (R10 proven, 52us): split-K Kc=256, grid (2,2,145); 64x64 tile
// =====================================================================
__global__ __launch_bounds__(256) void fc1_k(const float* __restrict__ hist,
                                             const float* __restrict__ w1) {
    __shared__ __align__(16) float Xs[32 * 68];
    __shared__ __align__(16) float Ws[32 * 68];
    const int kb = blockIdx.z, b0 = blockIdx.x * 64, j0 = blockIdx.y * 64;
    const int tid = threadIdx.x;
    const int klen = (kb == 144) ? 90 : 256;
    const int kbase = kb * 256;
    const int tb = tid & 15, tj = tid >> 4;
    ull acc[4][2];
#pragma unroll
    for (int i = 0; i < 4; i++) { acc[i][0] = 0ull; acc[i][1] = 0ull; }

    for (int ks = 0; ks < klen; ks += 32) {
        __syncthreads();
#pragma unroll
        for (int i = 0; i < 4; i++) {
            int e = tid + i * 256;
            int b = e >> 4, kh = e & 15;
            int k = ks + kh * 2;
            float2 xv = make_float2(0.f, 0.f), wv = make_float2(0.f, 0.f);
            if (k < klen) {
                xv = (kb == 144) ? *(const float2*)&hist[(b0 + b) * 90 + k]
                                 : *(const float2*)&g_a3[(b0 + b) * 36864 + kbase + k];
                wv = *(const float2*)&w1[(j0 + b) * 36954 + kbase + k];
            }
            Xs[(kh * 2) * 68 + b] = xv.x;
            Xs[(kh * 2 + 1) * 68 + b] = xv.y;
            Ws[(kh * 2) * 68 + b] = wv.x;
            Ws[(kh * 2 + 1) * 68 + b] = wv.y;
        }
        __syncthreads();
#pragma unroll
        for (int kk = 0; kk < 32; kk++) {
            ulonglong2 W = *(const ulonglong2*)&Ws[kk * 68 + tj * 4];
#pragma unroll
            for (int i = 0; i < 4; i++) {
                ull xp = pk2(Xs[kk * 68 + tb * 4 + i]);
                acc[i][0] = fma2(xp, W.x, acc[i][0]);
                acc[i][1] = fma2(xp, W.y, acc[i][1]);
            }
        }
    }
#pragma unroll
    for (int i = 0; i < 4; i++) {
        float* op = &g_part[(kb * 128 + b0 + tb * 4 + i) * 128 + j0 + tj * 4];
        float lo, hi;
        unpk(acc[i][0], lo, hi);
        op[0] = lo; op[1] = hi;
        unpk(acc[i][1], lo, hi);
        op[2] = lo; op[3] = hi;
    }
}

// =====================================================================
__global__ __launch_bounds__(256) void lif1_k(const float* __restrict__ b1) {
    int gid = blockIdx.x * 256 + threadIdx.x;
    int j = gid & 127;
    float h = b1[j];
#pragma unroll
    for (int kb = 0; kb < 145; kb++) h += g_part[kb * 16384 + gid];
    float mem = 0.f, syn = 0.f;
#pragma unroll
    for (int t = 0; t < 10; t++) {
        syn = ALPHA * syn + h;
        mem = BETA * mem + syn;
        float s = (mem > TH) ? 1.f : 0.f;
        mem -= s * TH;
        g_spk1[t * 16384 + gid] = s;
    }
}

// =====================================================================
__global__ __launch_bounds__(256) void gemm2_k(const float* __restrict__ w2,
                                               const float* __restrict__ b2) {
    __shared__ float Xs[64][33];
    __shared__ float Ws[64][33];
    const int m0 = blockIdx.x * 64, j0 = blockIdx.y * 64, tid = threadIdx.x;
    const int mi0 = (tid & 15) * 4, ji0 = (tid >> 4) * 4;
    float acc[4][4];
#pragma unroll
    for (int i = 0; i < 4; i++)
#pragma unroll
        for (int j = 0; j < 4; j++) acc[i][j] = 0.f;

    for (int ks = 0; ks < 128; ks += 32) {
        __syncthreads();
#pragma unroll
        for (int i = 0; i < 8; i++) {
            int e = tid + i * 256, r = e >> 5, kk = e & 31;
            Xs[r][kk] = g_spk1[(m0 + r) * 128 + ks + kk];
            Ws[r][kk] = w2[(j0 + r) * 128 + ks + kk];
        }
        __syncthreads();
#pragma unroll
        for (int kk = 0; kk < 32; kk++) {
            float xv[4], wv[4];
#pragma unroll
            for (int i = 0; i < 4; i++) xv[i] = Xs[mi0 + i][kk];
#pragma unroll
            for (int j = 0; j < 4; j++) wv[j] = Ws[ji0 + j][kk];
#pragma unroll
            for (int i = 0; i < 4; i++)
#pragma unroll
                for (int j = 0; j < 4; j++) acc[i][j] += xv[i] * wv[j];
        }
    }
#pragma unroll
    for (int i = 0; i < 4; i++)
#pragma unroll
        for (int j = 0; j < 4; j++)
            g_h2[(m0 + mi0 + i) * 256 + j0 + ji0 + j] = acc[i][j] + b2[j0 + ji0 + j];
}

// =====================================================================
__global__ __launch_bounds__(256) void lif2_k() {
    int b = blockIdx.x, j = threadIdx.x;
    float mem = 0.f, syn = 0.f;
#pragma unroll
    for (int t = 0; t < 10; t++) {
        float h = g_h2[(t * 128 + b) * 256 + j];
        syn = ALPHA * syn + h;
        mem = BETA * mem + syn;
        float s = (mem > TH) ? 1.f : 0.f;
        mem -= s * TH;
        g_spk2[(t * 128 + b) * 256 + j] = s;
    }
}

// =====================================================================
__global__ __launch_bounds__(96) void out_k(const float* __restrict__ w3,
                                            const float* __restrict__ b3,
                                            float* __restrict__ out) {
    __shared__ float s_s[10 * 256];
    __shared__ float s_w[9 * 256];
    __shared__ float s_h[90];
    const int b = blockIdx.x, tid = threadIdx.x;

    for (int idx = tid; idx < 2560; idx += 96) {
        int t = idx >> 8, k = idx & 255;
        s_s[idx] = g_spk2[(t * 128 + b) * 256 + k];
    }
    for (int idx = tid; idx < 2304; idx += 96) s_w[idx] = w3[idx];
    __syncthreads();

    if (tid < 90) {
        int t = tid / 9, o = tid % 9;
        float a = b3[o];
        for (int k = 0; k < 256; k++) a += s_s[t * 256 + k] * s_w[o * 256 + k];
        s_h[tid] = a;
    }
    __syncthreads();

    if (tid < 9) {
        float syn = 0.f, mem = 0.f, pot = 0.f;
#pragma unroll
        for (int t = 0; t < 10; t++) {
            syn = ALPHA * syn + s_h[t * 9 + tid];
            mem = BETA * mem + syn;
            pot += mem;
        }
        out[b * 9 + tid] = pot / 10.0f;
    }
}

// =====================================================================
extern "C" void kernel_launch(void* const* d_in, const int* in_sizes, int n_in,
                              void* d_out, int out_size) {
    const float* state = (const float*)d_in[0];
    const float* hist  = (const float*)d_in[1];
    const float* cw1 = (const float*)d_in[2];
    const float* cb1 = (const float*)d_in[3];
    const float* cw2 = (const float*)d_in[4];
    const float* cb2 = (const float*)d_in[5];
    const float* cw3 = (const float*)d_in[6];
    const float* cb3 = (const float*)d_in[7];
    const float* w1  = (const float*)d_in[8];
    const float* b1  = (const float*)d_in[9];
    const float* w2  = (const float*)d_in[10];
    const float* b2  = (const float*)d_in[11];
    const float* w3  = (const float*)d_in[12];
    const float* b3  = (const float*)d_in[13];
    float* out = (float*)d_out;

    const int smem1 = 79296, smem2 = 52736, smem3 = 49920;
    cudaFuncSetAttribute(conv1_k, cudaFuncAttributeMaxDynamicSharedMemorySize, smem1);
    cudaFuncSetAttribute(conv2_k, cudaFuncAttributeMaxDynamicSharedMemorySize, smem2);
    cudaFuncSetAttribute(conv3_k, cudaFuncAttributeMaxDynamicSharedMemorySize, smem3);

    // keep the ncu capture window on conv1_k
    dummy_k<<<1, 32>>>(0);
    dummy_k<<<1, 32>>>(1);
    dummy_k<<<1, 32>>>(2);

    conv1_k<<<dim3(14, 128), 512, smem1>>>(state, cw1, cb1);
    conv2_k<<<dim3(7, 128), 256, smem2>>>(cw2, cb2);
    conv3_k<<<dim3(6, 128), 256, smem3>>>(cw3, cb3);
    fc1_k<<<dim3(2, 2, 145), 256>>>(hist, w1);
    lif1_k<<<64, 256>>>(b1);
    gemm2_k<<<dim3(20, 4), 256>>>(w2, b2);
    lif2_k<<<128, 256>>>();
    out_k<<<128, 96>>>(w3, b3, out);
}